// round 9
// baseline (speedup 1.0000x reference)
#include <cuda_runtime.h>
#include <cuda_bf16.h>
#include <cstdint>

// ============================================================
// PINN fwd + 1st/2nd derivatives via mma.sync (HMMA) bf16 hi/lo
//   CTA: 16 samples, 512 threads (16 warps, 1 j-tile of 16 rows each).
//   State S[i][c] bf16 hi/lo in SMEM, c=q*16+s (112 cols).
//   Hidden layer: D[j,c] = sum_i W[i,j]*S[i,c]; M=256, N=112, K=256.
//   3 passes Whi*Shi + Whi*Slo + Wlo*Shi accumulated in fp32 registers.
// ============================================================

#define THREADS 512
#define SB 16
#define CT 14                 // c-tiles of 8
#define BROW 240              // bytes per state row (112*2 = 224 + 16 pad)
#define BHALF (256 * BROW)    // 61440 per half

#define SM_BHI 0
#define SM_BLO BHALF
#define SM_W4   (2 * BHALF)         // 122880 : w4t[o][i] f32, 2048 B
#define SM_BIAS (SM_W4 + 2048)      // 124928 : b1,b2,b3 f32, 3072 B
#define SM_TOTAL (SM_BIAS + 3072)   // 128000
// final-layer fp32 state overlays BHI/BLO: S3f[c][i], row stride 1040 B
#define S3STRIDE 260                // floats per row (256 + 4 pad)

// pre-transposed weights: WtH/WtL[L][j][i] bf16, j,i in [0,256)
__device__ uint16_t g_WtH[3 * 256 * 256];
__device__ uint16_t g_WtL[3 * 256 * 256];

__device__ __forceinline__ uint32_t smem_u32(const void* p) {
    uint32_t a;
    asm("{ .reg .u64 t; cvta.to.shared.u64 t, %1; cvt.u32.u64 %0, t; }"
        : "=r"(a) : "l"(p));
    return a;
}
__device__ __forceinline__ void ldmB4(uint32_t* b, uint32_t addr) {
    asm volatile("ldmatrix.sync.aligned.m8n8.x4.trans.shared.b16 {%0,%1,%2,%3}, [%4];"
                 : "=r"(b[0]), "=r"(b[1]), "=r"(b[2]), "=r"(b[3]) : "r"(addr));
}
__device__ __forceinline__ void mma16816(float* d, const uint32_t* a,
                                         uint32_t b0, uint32_t b1) {
    asm volatile(
        "mma.sync.aligned.m16n8k16.row.col.f32.bf16.bf16.f32 "
        "{%0,%1,%2,%3}, {%4,%5,%6,%7}, {%8,%9}, {%0,%1,%2,%3};"
        : "+f"(d[0]), "+f"(d[1]), "+f"(d[2]), "+f"(d[3])
        : "r"(a[0]), "r"(a[1]), "r"(a[2]), "r"(a[3]), "r"(b0), "r"(b1));
}
__device__ __forceinline__ uint32_t pk2(float a, float b) {
    return (uint32_t)__bfloat16_as_ushort(__float2bfloat16(a)) |
           ((uint32_t)__bfloat16_as_ushort(__float2bfloat16(b)) << 16);
}

// ---------------- prep: W[L] (i-major) -> Wt[L][j][i] bf16 hi/lo ----------
__global__ void __launch_bounds__(256) prep_kernel(
    const float* __restrict__ W1, const float* __restrict__ W2,
    const float* __restrict__ W3)
{
    int idx = blockIdx.x * 256 + threadIdx.x;   // = L*65536 + j*256 + i
    int L = idx >> 16;
    int j = (idx >> 8) & 255;
    int i = idx & 255;
    const float* W = (L == 0) ? W1 : ((L == 1) ? W2 : W3);
    float v = W[i * 256 + j];
    __nv_bfloat16 hb = __float2bfloat16(v);
    float lo = v - __bfloat162float(hb);
    g_WtH[idx] = __bfloat16_as_ushort(hb);
    g_WtL[idx] = __bfloat16_as_ushort(__float2bfloat16(lo));
}

// ---------------- main kernel ----------------
__global__ void __launch_bounds__(THREADS, 1) pinn_mma_kernel(
    const float* __restrict__ x,
    const float* __restrict__ W0, const float* __restrict__ b0_,
    const float* __restrict__ b1_, const float* __restrict__ b2_,
    const float* __restrict__ b3_,
    const float* __restrict__ W4, const float* __restrict__ b4,
    const float* __restrict__ lb, const float* __restrict__ ub,
    float* __restrict__ out, int N)
{
    extern __shared__ char sm[];
    const uint32_t smb = smem_u32(sm);
    const int tid  = threadIdx.x;
    const int warp = tid >> 5, lane = tid & 31;
    const int g = lane >> 2, tg = lane & 3;
    const int s0 = blockIdx.x * SB;

    // stage W4 transposed (w4t[o][i]) and hidden biases
    if (tid < 512)
        ((float*)(sm + SM_W4))[(tid & 1) * 256 + (tid >> 1)] = W4[tid];
    if (tid < 256) {
        ((float*)(sm + SM_BIAS))[tid]       = b1_[tid];
        ((float*)(sm + SM_BIAS))[256 + tid] = b2_[tid];
        ((float*)(sm + SM_BIAS))[512 + tid] = b3_[tid];
    }

    // ---------- layer 0: 3 -> 256 (SIMT), write bf16 hi/lo state ----------
    {
        float lbv[3], sk[3];
#pragma unroll
        for (int k = 0; k < 3; k++) { lbv[k] = lb[k]; sk[k] = 2.0f / (ub[k] - lb[k]); }
        const int j = tid & 255;
        const int h = tid >> 8;          // sample-half split across the 512 threads
        float w[3];
#pragma unroll
        for (int k = 0; k < 3; k++) w[k] = W0[k * 256 + j];
        const float bj = b0_[j];
        float zj[3], Szl = 0.0f;
#pragma unroll
        for (int k = 0; k < 3; k++) { zj[k] = w[k] * sk[k]; Szl += zj[k]; }
#pragma unroll
        for (int spp = 0; spp < 4; spp++) {
            const int sp = h * 4 + spp;
            float v[2][7];
#pragma unroll
            for (int p = 0; p < 2; p++) {
                const int s = 2 * sp + p;
                float xn0 = sk[0] * (x[(s0 + s) * 3 + 0] - lbv[0]) - 1.0f;
                float xn1 = sk[1] * (x[(s0 + s) * 3 + 1] - lbv[1]) - 1.0f;
                float xn2 = sk[2] * (x[(s0 + s) * 3 + 2] - lbv[2]) - 1.0f;
                float z = bj + w[0] * xn0 + w[1] * xn1 + w[2] * xn2;
                float t = tanhf(z);
                float gg = 1.0f - t * t;
                float u = -2.0f * t * gg * Szl;
                v[p][0] = t;
#pragma unroll
                for (int k = 0; k < 3; k++) { v[p][1 + k] = gg * zj[k]; v[p][4 + k] = u * zj[k]; }
            }
#pragma unroll
            for (int q = 0; q < 7; q++) {
                const int off = j * BROW + 32 * q + 4 * sp;   // col = 16q + 2sp
                float h0 = __bfloat162float(__float2bfloat16(v[0][q]));
                float h1 = __bfloat162float(__float2bfloat16(v[1][q]));
                *(uint32_t*)(sm + SM_BHI + off) = pk2(v[0][q], v[1][q]);
                *(uint32_t*)(sm + SM_BLO + off) = pk2(v[0][q] - h0, v[1][q] - h1);
            }
        }
    }
    __syncthreads();

    // ---------- hidden layers 1..3 via mma.sync ----------
    const int jt = warp;                 // one 16-row j-tile per warp
#pragma unroll 1
    for (int L = 0; L < 3; L++) {
        const uint16_t* __restrict__ WH = g_WtH + L * 65536;
        const uint16_t* __restrict__ WL = g_WtL + L * 65536;

        float acc[CT][4];
#pragma unroll
        for (int ct = 0; ct < CT; ct++)
#pragma unroll
            for (int d = 0; d < 4; d++) acc[ct][d] = 0.0f;

#pragma unroll 1
        for (int kb = 0; kb < 8; kb++) {
            uint32_t aH[2][4], aL[2][4];
            const int jbase = jt * 16;
#pragma unroll
            for (int kk = 0; kk < 2; kk++) {
                const int i0 = kb * 32 + kk * 16 + 2 * tg;
                const uint16_t* pH = WH + (jbase + g) * 256 + i0;
                const uint16_t* pL = WL + (jbase + g) * 256 + i0;
                aH[kk][0] = *(const uint32_t*)(pH);
                aH[kk][1] = *(const uint32_t*)(pH + 8 * 256);
                aH[kk][2] = *(const uint32_t*)(pH + 8);
                aH[kk][3] = *(const uint32_t*)(pH + 8 * 256 + 8);
                aL[kk][0] = *(const uint32_t*)(pL);
                aL[kk][1] = *(const uint32_t*)(pL + 8 * 256);
                aL[kk][2] = *(const uint32_t*)(pL + 8);
                aL[kk][3] = *(const uint32_t*)(pL + 8 * 256 + 8);
            }
#pragma unroll
            for (int ct = 0; ct < CT; ct++) {
                // x4 ldmatrix: 32 consecutive K-rows, lanes 0..31 -> rows
                const uint32_t baddr = smb + SM_BHI +
                    (uint32_t)(kb * 32 * BROW) + (uint32_t)(lane * BROW) + ct * 16;
                uint32_t bh[4], bl[4];
                ldmB4(bh, baddr);
                ldmB4(bl, baddr + BHALF);
                mma16816(acc[ct], aH[0], bh[0], bh[1]);
                mma16816(acc[ct], aH[1], bh[2], bh[3]);
                mma16816(acc[ct], aH[0], bl[0], bl[1]);
                mma16816(acc[ct], aH[1], bl[2], bl[3]);
                mma16816(acc[ct], aL[0], bh[0], bh[1]);
                mma16816(acc[ct], aL[1], bh[2], bh[3]);
            }
        }
        __syncthreads();   // all reads of old state done

        // ---------- elementwise (thread-local) ----------
        const float* bias = (const float*)(sm + SM_BIAS) + L * 256;
        const bool last = (L == 2);
#pragma unroll
        for (int r = 0; r < 2; r++) {
            const int j = jt * 16 + g + 8 * r;
            const float bj = bias[j];
#pragma unroll
            for (int slp = 0; slp < 2; slp++) {
                float v[2][7];
#pragma unroll
                for (int p = 0; p < 2; p++) {
                    const int d = 2 * r + p;
                    float zh = acc[slp][d] + bj;
                    float z0 = acc[2 + slp][d];
                    float z1 = acc[4 + slp][d];
                    float z2 = acc[6 + slp][d];
                    float t0 = acc[8 + slp][d];
                    float t1 = acc[10 + slp][d];
                    float t2 = acc[12 + slp][d];
                    float t = tanhf(zh);
                    float gg = 1.0f - t * t;
                    float Sz = z0 + z1 + z2;
                    float u = -2.0f * t * gg * Sz;
                    v[p][0] = t;
                    v[p][1] = gg * z0; v[p][2] = gg * z1; v[p][3] = gg * z2;
                    v[p][4] = u * z0 + gg * t0;
                    v[p][5] = u * z1 + gg * t1;
                    v[p][6] = u * z2 + gg * t2;
                }
                const int se = 2 * tg + 8 * slp;   // even sample index
                if (!last) {
#pragma unroll
                    for (int q = 0; q < 7; q++) {
                        const int off = j * BROW + (16 * q + se) * 2;
                        float h0 = __bfloat162float(__float2bfloat16(v[0][q]));
                        float h1 = __bfloat162float(__float2bfloat16(v[1][q]));
                        *(uint32_t*)(sm + SM_BHI + off) = pk2(v[0][q], v[1][q]);
                        *(uint32_t*)(sm + SM_BLO + off) = pk2(v[0][q] - h0, v[1][q] - h1);
                    }
                } else {
#pragma unroll
                    for (int q = 0; q < 7; q++) {
                        ((float*)sm)[(16 * q + se) * S3STRIDE + j]     = v[0][q];
                        ((float*)sm)[(16 * q + se + 1) * S3STRIDE + j] = v[1][q];
                    }
                }
            }
        }
        __syncthreads();
    }

    // ---------- final layer: 256 -> 2 ----------
    if (tid < 224) {
        const int o = tid & 1, c = tid >> 1;
        const float4* row = reinterpret_cast<const float4*>(sm + (size_t)c * (S3STRIDE * 4));
        const float4* wr  = reinterpret_cast<const float4*>(sm + SM_W4 + o * 1024);
        float sum = 0.0f;
#pragma unroll 8
        for (int i4 = 0; i4 < 64; i4++) {
            float4 a = row[i4];
            float4 b = wr[i4];
            sum += a.x * b.x + a.y * b.y + a.z * b.z + a.w * b.w;
        }
        const int q = c >> 4, s = c & 15;
        const int n = s0 + s;
        if (q == 0) {
            out[n * 2 + o] = sum + b4[o];
        } else if (q < 4) {
            out[2 * N + o * 3 * N + n * 3 + (q - 1)] = sum;
        } else {
            out[8 * N + o * 3 * N + n * 3 + (q - 4)] = sum;
        }
    }
}

extern "C" void kernel_launch(void* const* d_in, const int* in_sizes, int n_in,
                              void* d_out, int out_size)
{
    const float* x  = (const float*)d_in[0];
    const float* W0 = (const float*)d_in[1];
    const float* b0 = (const float*)d_in[2];
    const float* W1 = (const float*)d_in[3];
    const float* b1 = (const float*)d_in[4];
    const float* W2 = (const float*)d_in[5];
    const float* b2 = (const float*)d_in[6];
    const float* W3 = (const float*)d_in[7];
    const float* b3 = (const float*)d_in[8];
    const float* W4 = (const float*)d_in[9];
    const float* b4 = (const float*)d_in[10];
    const float* lb = (const float*)d_in[11];
    const float* ub = (const float*)d_in[12];
    float* out = (float*)d_out;

    const int N = in_sizes[0] / 3;          // 32768

    prep_kernel<<<3 * 256 * 256 / 256, 256>>>(W1, W2, W3);

    cudaFuncSetAttribute(pinn_mma_kernel,
                         cudaFuncAttributeMaxDynamicSharedMemorySize, SM_TOTAL);
    pinn_mma_kernel<<<N / SB, THREADS, SM_TOTAL>>>(
        x, W0, b0, b1, b2, b3, W4, b4, lb, ub, out, N);
}